// round 12
// baseline (speedup 1.0000x reference)
#include <cuda_runtime.h>
#include <math.h>
#include <float.h>

#define BATCH   256
#define NLEV    4
#define CDIM    8000
#define NTOTAL  10500
#define THREADS 256

// Cross-half combine state (zero-initialized device globals; finishers reset
// them every launch so graph replays see zeros again).
// g_fsum[b][l-1]: exp-sum for level l (1..3). Exactly 2 atomicAdd contributors
//                 per value -> order-independent (a+b == b+a) -> deterministic.
// g_key[b][l]:    monotone (value, first-index) key, atomicMax -> deterministic.
__device__ float              g_fsum[BATCH][3];
__device__ unsigned long long g_key[BATCH][4];
__device__ unsigned int       g_rowcnt[BATCH];
__device__ unsigned long long g_acc = 0ULL;   // packed fixed-point sum + count

__device__ __forceinline__ unsigned long long amax_key(float v, int idx) {
    unsigned u = __float_as_uint(v);
    u = (u & 0x80000000u) ? ~u : (u | 0x80000000u);   // order-preserving
    return ((unsigned long long)u << 32) | (unsigned)(0x7fffffff - idx);
}

__device__ __forceinline__ void acc4(float4 w, int e, bool pred,
                                     float& s, float& av, int& ai) {
    if (!pred) { w.x = w.y = w.z = w.w = -FLT_MAX; }  // exp->0, never argmax
    s += __expf(w.x); if (w.x > av) { av = w.x; ai = e + 0; }
    s += __expf(w.y); if (w.y > av) { av = w.y; ai = e + 1; }
    s += __expf(w.z); if (w.z > av) { av = w.z; ai = e + 2; }
    s += __expf(w.w); if (w.w > av) { av = w.w; ai = e + 3; }
}

__device__ __forceinline__ void comb(float& av, int& ai, float av2, int ai2) {
    if (av2 > av || (av2 == av && ai2 < ai)) { av = av2; ai = ai2; }
}

__device__ __forceinline__ void wred3(float& s, float& av, int& ai) {
    #pragma unroll
    for (int o = 16; o > 0; o >>= 1) {
        float s2  = __shfl_down_sync(0xffffffffu, s,  o);
        float av2 = __shfl_down_sync(0xffffffffu, av, o);
        int   ai2 = __shfl_down_sync(0xffffffffu, ai, o);
        s += s2;
        comb(av, ai, av2, ai2);
    }
}

__global__ void __launch_bounds__(THREADS, 4) taxa_half_kernel(
    const float* __restrict__ y_pred,
    const int*   __restrict__ y_true,
    const float* __restrict__ H,
    float*       __restrict__ out)
{
    const int bh   = blockIdx.x;
    const int b    = bh >> 1;
    const int h    = bh & 1;
    const int tid  = threadIdx.x;
    const int warp = tid >> 5;
    const int lane = tid & 31;

    __shared__ float s_s[3][8], s_av[3][8];
    __shared__ int   s_ai[3][8];
    __shared__ float s_tlogit[4];

    const float*  base = y_pred + (size_t)b * NLEV * CDIM;
    const float4* b4   = reinterpret_cast<const float4*>(base);

    // tlogit chain (tid 248..250): y_true load first so it overlaps the sweep.
    int tl_tgt = -1, tl_jj = 0;
    if (tid >= 248 && tid <= 250) {
        tl_jj = tid - 247;                       // 1..3
        const int szs = (tl_jj == 1) ? 400 : (tl_jj == 2) ? 2000 : 8000;
        int t = __ldg(&y_true[b * NLEV + tl_jj]);
        tl_tgt = min(max(t, 0), szs - 1);
    }

    // ---- Issue all sweep loads up-front (6 per thread) ----
    // L3 half: 1000 f4 at f4-offset 6000 + h*1000
    float4 v3[4]; int e3[4]; bool p3[4];
    #pragma unroll
    for (int k = 0; k < 4; k++) {
        int idx = tid + k * 256;
        p3[k] = idx < 1000;
        int id = p3[k] ? idx : 999;
        e3[k]  = 4 * (h * 1000 + id);
        v3[k]  = __ldg(b4 + 6000 + h * 1000 + id);
    }
    // L2 half: 250 f4 at 4000 + h*250
    bool p2 = tid < 250;
    int  id2 = p2 ? tid : 249;
    int  e2  = 4 * (h * 250 + id2);
    float4 v2 = __ldg(b4 + 4000 + h * 250 + id2);
    // Third segment: h0 -> L1 (100 f4 at 2000), h1 -> L0 (25 f4 at 0, argmax only)
    bool px; int idx_, ex;
    if (h == 0) { px = tid < 100; idx_ = px ? tid : 99; }
    else        { px = tid < 25;  idx_ = px ? tid : 24; }
    ex = 4 * idx_;
    float4 vx = __ldg(b4 + (h == 0 ? 2000 : 0) + idx_);

    // Dependent tlogit gather (overlaps the sweep-math below for other threads).
    if (tl_tgt >= 0)
        s_tlogit[tl_jj] = __ldg(base + (size_t)tl_jj * CDIM + tl_tgt);

    // ---- Accumulate ----
    float s3 = 0.f, av3 = -FLT_MAX; int ai3 = 0x7fffffff;
    #pragma unroll
    for (int k = 0; k < 4; k++) acc4(v3[k], e3[k], p3[k], s3, av3, ai3);

    float s2 = 0.f, av2 = -FLT_MAX; int ai2 = 0x7fffffff;
    acc4(v2, e2, p2, s2, av2, ai2);

    float sx = 0.f, avx = -FLT_MAX; int aix = 0x7fffffff;
    if (h == 0) {
        acc4(vx, ex, px, sx, avx, aix);
    } else {
        float4 w = vx;
        if (!px) { w.x = w.y = w.z = w.w = -FLT_MAX; }
        if (w.x > avx) { avx = w.x; aix = ex + 0; }
        if (w.y > avx) { avx = w.y; aix = ex + 1; }
        if (w.z > avx) { avx = w.z; aix = ex + 2; }
        if (w.w > avx) { avx = w.w; aix = ex + 3; }
    }

    // ---- Warp reduce (3 independent triplets interleave) ----
    wred3(s3, av3, ai3);
    wred3(s2, av2, ai2);
    wred3(sx, avx, aix);
    if (lane == 0) {
        s_s[0][warp] = s3; s_av[0][warp] = av3; s_ai[0][warp] = ai3;
        s_s[1][warp] = s2; s_av[1][warp] = av2; s_ai[1][warp] = ai2;
        s_s[2][warp] = sx; s_av[2][warp] = avx; s_ai[2][warp] = aix;
    }
    __syncthreads();   // single block-wide barrier

    // ---- Warp 0: fold 3x8 partials; lane 0 publishes + maybe finishes ----
    if (warp == 0) {
        const int seg = lane >> 3;   // 0:L3 1:L2 2:Lx (only segs 0..2 valid)
        const int i   = lane & 7;
        float rs = 0.f, rav = -FLT_MAX; int rai = 0x7fffffff;
        if (seg < 3) { rs = s_s[seg][i]; rav = s_av[seg][i]; rai = s_ai[seg][i]; }
        #pragma unroll
        for (int o = 4; o > 0; o >>= 1) {
            float s2_  = __shfl_down_sync(0xffffffffu, rs,  o);
            float av2_ = __shfl_down_sync(0xffffffffu, rav, o);
            int   ai2_ = __shfl_down_sync(0xffffffffu, rai, o);
            if (i + o < 8) { rs += s2_; comb(rav, rai, av2_, ai2_); }
        }
        const unsigned FULL = 0xffffffffu;
        float S3 = __shfl_sync(FULL, rs,  0);
        float S2 = __shfl_sync(FULL, rs,  8);
        float Sx = __shfl_sync(FULL, rs, 16);
        float A3 = __shfl_sync(FULL, rav,  0); int I3 = __shfl_sync(FULL, rai,  0);
        float A2 = __shfl_sync(FULL, rav,  8); int I2 = __shfl_sync(FULL, rai,  8);
        float Ax = __shfl_sync(FULL, rav, 16); int Ix = __shfl_sync(FULL, rai, 16);

        if (lane == 0) {
            // Publish this half's contributions (independent addresses -> pipeline).
            atomicAdd(&g_fsum[b][2], S3);
            atomicMax(&g_key[b][3], amax_key(A3, I3));
            atomicAdd(&g_fsum[b][1], S2);
            atomicMax(&g_key[b][2], amax_key(A2, I2));
            if (h == 0) {
                atomicAdd(&g_fsum[b][0], Sx);
                atomicMax(&g_key[b][1], amax_key(Ax, Ix));
            } else {
                atomicMax(&g_key[b][0], amax_key(Ax, Ix));
            }
            __threadfence();
            unsigned r = atomicAdd(&g_rowcnt[b], 1u);

            if (r == 1) {
                // Second arriver: combined values are complete in L2.
                __threadfence();
                float sum3 = __ldcg(&g_fsum[b][2]);
                float sum2 = __ldcg(&g_fsum[b][1]);
                float sum1 = __ldcg(&g_fsum[b][0]);
                unsigned long long k0 = __ldcg(&g_key[b][0]);
                unsigned long long k1 = __ldcg(&g_key[b][1]);
                unsigned long long k2 = __ldcg(&g_key[b][2]);
                unsigned long long k3 = __ldcg(&g_key[b][3]);

                // Reset row state for the next graph replay.
                g_fsum[b][0] = 0.f; g_fsum[b][1] = 0.f; g_fsum[b][2] = 0.f;
                g_key[b][0] = 0ULL; g_key[b][1] = 0ULL;
                g_key[b][2] = 0ULL; g_key[b][3] = 0ULL;
                g_rowcnt[b] = 0u;

                const int g0 = (0x7fffffff - (int)(unsigned)(k0 & 0xffffffffu));
                const int g1 = (0x7fffffff - (int)(unsigned)(k1 & 0xffffffffu)) + 100;
                const int g2 = (0x7fffffff - (int)(unsigned)(k2 & 0xffffffffu)) + 500;
                const int g3 = (0x7fffffff - (int)(unsigned)(k3 & 0xffffffffu)) + 2500;

                float nll1 = __logf(sum1) - s_tlogit[1];
                float nll2 = __logf(sum2) - s_tlogit[2];
                float nll3 = __logf(sum3) - s_tlogit[3];

                float h01 = __ldg(&H[(size_t)g0 * NTOTAL + g1]);
                float h12 = __ldg(&H[(size_t)g1 * NTOTAL + g2]);
                float h23 = __ldg(&H[(size_t)g2 * NTOTAL + g3]);
                float c01 = (h01 == 1.0f) ? 1.0f : 0.0f;
                float c12 = (h12 == 1.0f) ? 1.0f : 0.0f;
                float c23 = (h23 == 1.0f) ? 1.0f : 0.0f;

                const float E    = 2.7182817459106445f;   // float32(np.e)
                const float invB = 1.0f / (float)BATCH;
                float p = 0.25f * (E * c01 + nll1 * invB)
                        + 0.15f * (E * c12 + nll2 * invB)
                        + 0.10f * (E * c23 + nll3 * invB);
                p = fmaxf(p, 0.0f);

                unsigned long long fx =
                    (unsigned long long)__float2ll_rn(p * 4294967296.0f);
                unsigned long long old = atomicAdd(&g_acc, fx + (1ULL << 48));
                if ((old >> 48) == BATCH - 1) {
                    unsigned long long tot = (old & 0xFFFFFFFFFFFFULL) + fx;
                    out[0] = (float)((double)tot * (1.0 / 4294967296.0));
                    g_acc = 0ULL;
                }
            }
        }
    }
}

extern "C" void kernel_launch(void* const* d_in, const int* in_sizes, int n_in,
                              void* d_out, int out_size) {
    const float* y_pred = (const float*)d_in[0];
    const int*   y_true = (const int*)d_in[1];
    const float* H      = (const float*)d_in[2];
    float*       out    = (float*)d_out;

    taxa_half_kernel<<<BATCH * 2, THREADS>>>(y_pred, y_true, H, out);
}

// round 13
// speedup vs baseline: 1.2294x; 1.2294x over previous
#include <cuda_runtime.h>
#include <math.h>
#include <float.h>

#define BATCH   256
#define NLEV    4
#define CDIM    8000
#define NTOTAL  10500
#define THREADS 512

// Packed accumulator: bits [0,48) fixed-point sum (x 2^32, all p >= 0),
// bits [48,..) arrival count. Integer adds commute exactly -> deterministic.
__device__ unsigned long long g_acc = 0ULL;

__device__ __forceinline__ void amax_comb(float& av, int& ai, float av2, int ai2) {
    if (av2 > av || (av2 == av && ai2 < ai)) { av = av2; ai = ai2; }
}

// FMA-pipe exp (no MUFU). Rel err <= ~5e-5; inputs clamped to >= -80.
__device__ __forceinline__ float fexp_poly(float x) {
    float t = fmaxf(x, -80.0f) * 1.4426950408889634f;
    float r = t + 12582912.0f;
    int   k = __float_as_int(r) - 0x4B400000;
    float f = t - (r - 12582912.0f);
    float p = 0.009618129107f;
    p = fmaf(p, f, 0.055504108664f);
    p = fmaf(p, f, 0.240226506959f);
    p = fmaf(p, f, 0.693147180560f);
    p = fmaf(p, f, 1.0f);
    return __int_as_float(__float_as_int(p) + (k << 23));
}

// Exp-sum + argmax over one level's prefix (N4 float4s); ITERS loads issued
// up-front. Even batches use MUFU __expf, odd batches use the FMA-pipe poly,
// so the two halves dual-issue on different pipes.
template<int N4, int STRIDE, int ITERS, bool NEED_SUM>
__device__ __forceinline__ void accum(const float4* __restrict__ row4, int lt,
                                      float& s, float& av, int& ai) {
    float4 v[ITERS]; int id[ITERS]; bool p[ITERS];
    #pragma unroll
    for (int k = 0; k < ITERS; k++) {
        int idx = lt + k * STRIDE;
        p[k]  = idx < N4;
        id[k] = p[k] ? idx : (N4 - 1);
        v[k]  = __ldg(&row4[id[k]]);
    }
    float s0 = 0.f, s1 = 0.f, s2 = 0.f, s3 = 0.f;
    float a0 = -FLT_MAX, a1 = -FLT_MAX, a2 = -FLT_MAX, a3 = -FLT_MAX;
    int   i0 = 0x7fffffff, i1 = 0x7fffffff, i2 = 0x7fffffff, i3 = 0x7fffffff;
    #pragma unroll
    for (int k = 0; k < ITERS; k++) {
        float4 w = v[k];
        if (!p[k]) { w.x = w.y = w.z = w.w = -FLT_MAX; }
        int e = 4 * id[k];
        if (NEED_SUM) {
            if ((k & 1) == 0) {
                s0 += __expf(w.x); s1 += __expf(w.y);
                s2 += __expf(w.z); s3 += __expf(w.w);
            } else {
                s0 += fexp_poly(w.x); s1 += fexp_poly(w.y);
                s2 += fexp_poly(w.z); s3 += fexp_poly(w.w);
            }
        }
        if (w.x > a0) { a0 = w.x; i0 = e + 0; }
        if (w.y > a1) { a1 = w.y; i1 = e + 1; }
        if (w.z > a2) { a2 = w.z; i2 = e + 2; }
        if (w.w > a3) { a3 = w.w; i3 = e + 3; }
    }
    s = (s0 + s1) + (s2 + s3);
    av = a0; ai = i0;
    amax_comb(av, ai, a1, i1);
    amax_comb(av, ai, a2, i2);
    amax_comb(av, ai, a3, i3);
}

__global__ void __launch_bounds__(THREADS, 2) fused_taxanet_kernel(
    const float* __restrict__ y_pred,
    const int*   __restrict__ y_true,
    const float* __restrict__ H,
    float*       __restrict__ out)
{
    const int b    = blockIdx.x;
    const int tid  = threadIdx.x;
    const int warp = tid >> 5;
    const int lane = tid & 31;

    __shared__ float s_s[16], s_av[16];
    __shared__ int   s_ai[16];
    __shared__ float s_tlogit[4];

    const float* base = y_pred + (size_t)b * NLEV * CDIM;

    if (warp == 15) {
        // Prefetch target logits (two dependent trips, hidden by the sweep).
        if (lane < 3) {
            const int jj  = lane + 1;
            const int szs = (jj == 1) ? 400 : (jj == 2) ? 2000 : 8000;
            int tgt = __ldg(&y_true[b * NLEV + jj]);
            tgt = min(max(tgt, 0), szs - 1);
            s_tlogit[jj] = __ldg(base + (size_t)jj * CDIM + tgt);
        }
        if (lane == 0) { s_s[15] = 0.f; s_av[15] = -FLT_MAX; s_ai[15] = 0x7fffffff; }
    } else {
        // Segments: warps [0,8)->L3, [8,12)->L2, [12,14)->L1, [14]->L0
        int j, seg_base;
        if (warp < 8)       { j = 3; seg_base = 0;  }
        else if (warp < 12) { j = 2; seg_base = 8;  }
        else if (warp < 14) { j = 1; seg_base = 12; }
        else                { j = 0; seg_base = 14; }
        const int lt = tid - seg_base * 32;

        const float4* row4 = reinterpret_cast<const float4*>(base + (size_t)j * CDIM);

        float s, av; int ai;
        if (j == 3)      accum<2000, 256, 8, true >(row4, lt, s, av, ai);
        else if (j == 2) accum< 500, 128, 4, true >(row4, lt, s, av, ai);
        else if (j == 1) accum< 100,  64, 2, true >(row4, lt, s, av, ai);
        else             accum<  25,  32, 1, false>(row4, lt, s, av, ai);

        #pragma unroll
        for (int o = 16; o > 0; o >>= 1) {
            float s2  = __shfl_down_sync(0xffffffffu, s,  o);
            float av2 = __shfl_down_sync(0xffffffffu, av, o);
            int   ai2 = __shfl_down_sync(0xffffffffu, ai, o);
            s += s2;
            amax_comb(av, ai, av2, ai2);
        }
        if (lane == 0) { s_s[warp] = s; s_av[warp] = av; s_ai[warp] = ai; }
    }
    __syncthreads();   // the ONLY block-wide barrier

    // Warp 0 finishes the whole block: segmented reduce, H gathers, one atomic.
    if (warp == 0) {
        float rs = 0.f, rav = -FLT_MAX; int rai = 0x7fffffff;
        if (lane < 16) { rs = s_s[lane]; rav = s_av[lane]; rai = s_ai[lane]; }
        const int segsz   = (lane < 8) ? 8 : (lane < 12) ? 4 : (lane < 14) ? 2 : 1;
        const int segbase = (lane < 8) ? 0 : (lane < 12) ? 8 : (lane < 14) ? 12 : 14;
        const int w = lane - segbase;
        #pragma unroll
        for (int o = 4; o > 0; o >>= 1) {
            float s2  = __shfl_down_sync(0xffffffffu, rs,  o);
            float av2 = __shfl_down_sync(0xffffffffu, rav, o);
            int   ai2 = __shfl_down_sync(0xffffffffu, rai, o);
            if (w + o < segsz) {
                rs += s2;
                amax_comb(rav, rai, av2, ai2);
            }
        }
        // Heads: lane0->L3, lane8->L2, lane12->L1, lane14->L0.
        float nllv = 0.f;
        if (lane == 0)       nllv = __logf(rs) - s_tlogit[3];
        else if (lane == 8)  nllv = __logf(rs) - s_tlogit[2];
        else if (lane == 12) nllv = __logf(rs) - s_tlogit[1];

        const unsigned FULL = 0xffffffffu;
        int   g3i = __shfl_sync(FULL, rai, 0);
        int   g2i = __shfl_sync(FULL, rai, 8);
        int   g1i = __shfl_sync(FULL, rai, 12);
        int   g0i = __shfl_sync(FULL, rai, 14);
        float nll3 = __shfl_sync(FULL, nllv, 0);
        float nll2 = __shfl_sync(FULL, nllv, 8);
        float nll1 = __shfl_sync(FULL, nllv, 12);

        if (lane == 0) {
            const int g0 = g0i;
            const int g1 = g1i + 100;
            const int g2 = g2i + 500;
            const int g3 = g3i + 2500;

            float h01 = __ldg(&H[(size_t)g0 * NTOTAL + g1]);
            float h12 = __ldg(&H[(size_t)g1 * NTOTAL + g2]);
            float h23 = __ldg(&H[(size_t)g2 * NTOTAL + g3]);
            float c01 = (h01 == 1.0f) ? 1.0f : 0.0f;
            float c12 = (h12 == 1.0f) ? 1.0f : 0.0f;
            float c23 = (h23 == 1.0f) ? 1.0f : 0.0f;

            const float E    = 2.7182817459106445f;   // float32(np.e)
            const float invB = 1.0f / (float)BATCH;
            float p = 0.25f * (E * c01 + nll1 * invB)
                    + 0.15f * (E * c12 + nll2 * invB)
                    + 0.10f * (E * c23 + nll3 * invB);
            p = fmaxf(p, 0.0f);   // mathematically guaranteed; guards fixed-point

            unsigned long long fx =
                (unsigned long long)__float2ll_rn(p * 4294967296.0f);   // * 2^32
            unsigned long long old = atomicAdd(&g_acc, fx + (1ULL << 48));
            if ((old >> 48) == BATCH - 1) {
                unsigned long long tot = (old & 0xFFFFFFFFFFFFULL) + fx;
                out[0] = (float)((double)tot * (1.0 / 4294967296.0));
                g_acc = 0ULL;   // reset for graph replay
            }
        }
    }
}

extern "C" void kernel_launch(void* const* d_in, const int* in_sizes, int n_in,
                              void* d_out, int out_size) {
    const float* y_pred = (const float*)d_in[0];
    const int*   y_true = (const int*)d_in[1];
    const float* H      = (const float*)d_in[2];
    float*       out    = (float*)d_out;

    fused_taxanet_kernel<<<BATCH, THREADS>>>(y_pred, y_true, H, out);
}